// round 2
// baseline (speedup 1.0000x reference)
#include <cuda_runtime.h>
#include <cuda_bf16.h>

#define N_NODES 50000
#define N_EDGES 800000
#define D       128
#define N_GR    64

// -------- device scratch (no allocations allowed) --------
__device__ float g_deg [N_NODES];
__device__ float g_dinv[N_NODES];
__device__ int   g_cnt [N_NODES];
__device__ int   g_cur [N_NODES];
__device__ int   g_off [N_NODES + 1];
__device__ int   g_src [N_EDGES];
__device__ float g_nrm [N_EDGES];
__device__ float g_bufA[N_NODES * D];   // GEMM output (pre-aggregation features)
__device__ float g_bufB[N_NODES * D];   // aggregated + relu features (h1)
__device__ float g_pool[N_GR * D];
__device__ int   g_gcnt[N_GR];

// -------- init accumulators (runs every replay) --------
__global__ void init_kernel() {
    int i = blockIdx.x * blockDim.x + threadIdx.x;
    if (i < N_NODES) { g_deg[i] = 1.0f; g_cnt[i] = 0; g_cur[i] = 0; }
    if (i < N_GR * D) g_pool[i] = 0.0f;
    if (i < N_GR)     g_gcnt[i] = 0;
}

// -------- per-edge: degree sum + in-degree count --------
__global__ void edge_deg_kernel(const int* __restrict__ ei,
                                const float* __restrict__ ew) {
    int e = blockIdx.x * blockDim.x + threadIdx.x;
    if (e >= N_EDGES) return;
    int c = ei[N_EDGES + e];          // target node
    atomicAdd(&g_deg[c], ew[e]);
    atomicAdd(&g_cnt[c], 1);
}

// -------- per-node: dinv = rsqrt(deg), graph node counts --------
__global__ void dinv_kernel(const int* __restrict__ batch) {
    int i = blockIdx.x * blockDim.x + threadIdx.x;
    if (i >= N_NODES) return;
    g_dinv[i] = rsqrtf(g_deg[i]);     // deg >= 1 (self loop) always > 0
    atomicAdd(&g_gcnt[batch[i]], 1);
}

// -------- single-block exclusive scan over g_cnt -> g_off --------
__global__ void scan_kernel() {
    __shared__ int s[1024];
    const int t = threadIdx.x;
    const int CH = (N_NODES + 1023) / 1024;   // 49
    int begin = t * CH;
    int end   = begin + CH; if (end > N_NODES) end = N_NODES;
    int sum = 0;
    for (int i = begin; i < end; i++) sum += g_cnt[i];
    s[t] = sum;
    __syncthreads();
    // Hillis-Steele inclusive scan
    for (int d = 1; d < 1024; d <<= 1) {
        int v = (t >= d) ? s[t - d] : 0;
        __syncthreads();
        s[t] += v;
        __syncthreads();
    }
    int run = s[t] - sum;   // exclusive prefix
    for (int i = begin; i < end; i++) { g_off[i] = run; run += g_cnt[i]; }
    if (t == 1023) g_off[N_NODES] = run;   // = N_EDGES
}

// -------- fill CSR: sorted-by-target src ids + precomputed norms --------
__global__ void fill_kernel(const int* __restrict__ ei,
                            const float* __restrict__ ew) {
    int e = blockIdx.x * blockDim.x + threadIdx.x;
    if (e >= N_EDGES) return;
    int r = ei[e];
    int c = ei[N_EDGES + e];
    int pos = g_off[c] + atomicAdd(&g_cur[c], 1);
    g_src[pos] = r;
    g_nrm[pos] = g_dinv[r] * ew[e] * g_dinv[c];
}

// -------- GEMM: Y[50000,128] = X[50000,128] @ W[128,128], fp32 --------
// block = 256 threads, computes 16 rows x 64 cols; grid = (3125, 2)
__global__ __launch_bounds__(256) void gemm_kernel(const float* __restrict__ Xext,
                                                   const float* __restrict__ W,
                                                   int srcSel) {
    __shared__ float Wsh[128 * 64];
    __shared__ float Xsh[16 * 128];
    const float* X = (srcSel == 0) ? Xext : g_bufB;
    float* Y = g_bufA;

    const int t = threadIdx.x;
    const int rowBase = blockIdx.x * 16;
    const int colBase = blockIdx.y * 64;

    const float4* W4 = reinterpret_cast<const float4*>(W);
    float4* Wsh4 = reinterpret_cast<float4*>(Wsh);
#pragma unroll
    for (int r = 0; r < 8; r++) {
        int q = t + 256 * r;            // 0..2047 float4s
        int k = q >> 4, cf = q & 15;
        Wsh4[k * 16 + cf] = W4[k * 32 + (colBase >> 2) + cf];
    }
    const float4* X4 = reinterpret_cast<const float4*>(X);
    float4* Xsh4 = reinterpret_cast<float4*>(Xsh);
#pragma unroll
    for (int r = 0; r < 2; r++) {
        int q = t + 256 * r;            // 0..511 float4s
        int rr = q >> 5, cf = q & 31;
        Xsh4[rr * 32 + cf] = X4[(rowBase + rr) * 32 + cf];
    }
    __syncthreads();

    const int tx = t & 15, ty = t >> 4;
    float4 acc = make_float4(0.f, 0.f, 0.f, 0.f);
#pragma unroll
    for (int k = 0; k < 128; k++) {
        float a = Xsh[ty * 128 + k];
        float4 w = Wsh4[k * 16 + tx];
        acc.x = fmaf(a, w.x, acc.x);
        acc.y = fmaf(a, w.y, acc.y);
        acc.z = fmaf(a, w.z, acc.z);
        acc.w = fmaf(a, w.w, acc.w);
    }
    reinterpret_cast<float4*>(Y)[(rowBase + ty) * 32 + (colBase >> 2) + tx] = acc;
}

// -------- aggregation: warp per node; reads g_bufA --------
// out = relu( sum_{e in-edges} nrm_e * A[src_e] + dinv^2 * A[node] + bias )
// POOL=false: write g_bufB.  POOL=true: atomicAdd into g_pool[batch[node]].
template <bool POOL>
__global__ __launch_bounds__(256) void agg_kernel(const float* __restrict__ bias,
                                                  const int* __restrict__ batch) {
    const int node = blockIdx.x * 8 + (threadIdx.x >> 5);
    const int lane = threadIdx.x & 31;
    const float4* in4 = reinterpret_cast<const float4*>(g_bufA);

    float di = g_dinv[node];
    float s2 = di * di;
    float4 a = in4[node * 32 + lane];
    float4 acc = make_float4(s2 * a.x, s2 * a.y, s2 * a.z, s2 * a.w);

    int e  = g_off[node];
    int e1 = g_off[node + 1];
    for (; e + 1 < e1; e += 2) {
        int   s0 = g_src[e],     s1 = g_src[e + 1];
        float w0 = g_nrm[e],     w1 = g_nrm[e + 1];
        float4 v0 = in4[s0 * 32 + lane];
        float4 v1 = in4[s1 * 32 + lane];
        acc.x = fmaf(w0, v0.x, acc.x); acc.y = fmaf(w0, v0.y, acc.y);
        acc.z = fmaf(w0, v0.z, acc.z); acc.w = fmaf(w0, v0.w, acc.w);
        acc.x = fmaf(w1, v1.x, acc.x); acc.y = fmaf(w1, v1.y, acc.y);
        acc.z = fmaf(w1, v1.z, acc.z); acc.w = fmaf(w1, v1.w, acc.w);
    }
    if (e < e1) {
        int s0 = g_src[e]; float w0 = g_nrm[e];
        float4 v0 = in4[s0 * 32 + lane];
        acc.x = fmaf(w0, v0.x, acc.x); acc.y = fmaf(w0, v0.y, acc.y);
        acc.z = fmaf(w0, v0.z, acc.z); acc.w = fmaf(w0, v0.w, acc.w);
    }

    float4 b = reinterpret_cast<const float4*>(bias)[lane];
    acc.x = fmaxf(acc.x + b.x, 0.f);
    acc.y = fmaxf(acc.y + b.y, 0.f);
    acc.z = fmaxf(acc.z + b.z, 0.f);
    acc.w = fmaxf(acc.w + b.w, 0.f);

    if (POOL) {
        int g = batch[node];
        float* p = &g_pool[g * D + lane * 4];
        atomicAdd(p + 0, acc.x);
        atomicAdd(p + 1, acc.y);
        atomicAdd(p + 2, acc.z);
        atomicAdd(p + 3, acc.w);
    } else {
        reinterpret_cast<float4*>(g_bufB)[node * 32 + lane] = acc;
    }
}

// -------- head: out[g] = (pool[g]/count) . Wh + bh --------
__global__ void final_kernel(const float* __restrict__ Wh,
                             const float* __restrict__ bh,
                             float* __restrict__ out) {
    __shared__ float red[128];
    const int g = blockIdx.x;
    const int t = threadIdx.x;
    float c = (float)g_gcnt[g];
    c = fmaxf(c, 1.0f);
    float v = (g_pool[g * D + t] / c) * Wh[t];
    red[t] = v;
    __syncthreads();
    for (int s = 64; s > 0; s >>= 1) {
        if (t < s) red[t] += red[t + s];
        __syncthreads();
    }
    if (t == 0) out[g] = red[0] + bh[0];
}

extern "C" void kernel_launch(void* const* d_in, const int* in_sizes, int n_in,
                              void* d_out, int out_size) {
    const float* x     = (const float*)d_in[0];
    const float* ew    = (const float*)d_in[1];
    const float* W1    = (const float*)d_in[2];
    const float* b1    = (const float*)d_in[3];
    const float* W2    = (const float*)d_in[4];
    const float* b2    = (const float*)d_in[5];
    const float* Wh    = (const float*)d_in[6];
    const float* bh    = (const float*)d_in[7];
    const int*   ei    = (const int*)d_in[8];
    const int*   batch = (const int*)d_in[9];
    float*       out   = (float*)d_out;

    const int NB_N = (N_NODES + 255) / 256;   // 196
    const int NB_E = (N_EDGES + 255) / 256;   // 3125

    init_kernel<<<NB_N, 256>>>();
    edge_deg_kernel<<<NB_E, 256>>>(ei, ew);
    dinv_kernel<<<NB_N, 256>>>(batch);
    scan_kernel<<<1, 1024>>>();
    fill_kernel<<<NB_E, 256>>>(ei, ew);

    // layer 1: A = x @ W1 ; B = relu(agg(A) + b1)
    gemm_kernel<<<dim3(N_NODES / 16, 2), 256>>>(x, W1, 0);
    agg_kernel<false><<<N_NODES / 8, 256>>>(b1, batch);

    // layer 2: A = B @ W2 ; pooled += relu(agg(A) + b2)
    gemm_kernel<<<dim3(N_NODES / 16, 2), 256>>>(nullptr, W2, 1);
    agg_kernel<true><<<N_NODES / 8, 256>>>(b2, batch);

    final_kernel<<<N_GR, 128>>>(Wh, bh, out);
}

// round 3
// speedup vs baseline: 1.3483x; 1.3483x over previous
#include <cuda_runtime.h>
#include <cuda_bf16.h>

#define N_NODES 50000
#define N_EDGES 800000
#define D       128
#define N_GR    64
#define NB_SCAN 196   // ceil(50000/256)

// -------- device scratch (no allocations allowed) --------
__device__ float g_deg [N_NODES];
__device__ float g_dinv[N_NODES];
__device__ int   g_cnt [N_NODES];
__device__ int   g_cur [N_NODES];
__device__ int   g_off [N_NODES + 1];
__device__ int   g_bsum[256];
__device__ int   g_src [N_EDGES];
__device__ float g_nrm [N_EDGES];
__device__ float g_bufA[N_NODES * D];   // GEMM output (pre-aggregation features)
__device__ float g_bufB[N_NODES * D];   // aggregated + relu features (h1)
__device__ float g_pool[N_GR * D];
__device__ int   g_gcnt[N_GR];

// -------- init accumulators (runs every replay) --------
__global__ void init_kernel() {
    int i = blockIdx.x * blockDim.x + threadIdx.x;
    if (i < N_NODES) { g_deg[i] = 1.0f; g_cnt[i] = 0; g_cur[i] = 0; }
    if (i < N_GR * D) g_pool[i] = 0.0f;
    if (i < N_GR)     g_gcnt[i] = 0;
}

// -------- per-edge: degree sum + in-degree count --------
__global__ void edge_deg_kernel(const int* __restrict__ ei,
                                const float* __restrict__ ew) {
    int e = blockIdx.x * blockDim.x + threadIdx.x;
    if (e >= N_EDGES) return;
    int c = ei[N_EDGES + e];          // target node
    atomicAdd(&g_deg[c], ew[e]);
    atomicAdd(&g_cnt[c], 1);
}

// -------- per-node: dinv = rsqrt(deg), graph node counts --------
__global__ void dinv_kernel(const int* __restrict__ batch) {
    int i = blockIdx.x * blockDim.x + threadIdx.x;
    if (i >= N_NODES) return;
    g_dinv[i] = rsqrtf(g_deg[i]);     // deg >= 1 (self loop) always > 0
    atomicAdd(&g_gcnt[batch[i]], 1);
}

// -------- 3-pass parallel exclusive scan over g_cnt -> g_off --------
__global__ void scan1_kernel() {            // per-block sums
    __shared__ int s[256];
    int t = threadIdx.x;
    int i = blockIdx.x * 256 + t;
    int v = (i < N_NODES) ? g_cnt[i] : 0;
    s[t] = v;
    __syncthreads();
    for (int d = 128; d > 0; d >>= 1) {
        if (t < d) s[t] += s[t + d];
        __syncthreads();
    }
    if (t == 0) g_bsum[blockIdx.x] = s[0];
}

__global__ void scan2_kernel() {            // exclusive scan of block sums
    __shared__ int s[256];
    int t = threadIdx.x;
    int v = (t < NB_SCAN) ? g_bsum[t] : 0;
    s[t] = v;
    __syncthreads();
    for (int d = 1; d < 256; d <<= 1) {
        int u = (t >= d) ? s[t - d] : 0;
        __syncthreads();
        s[t] += u;
        __syncthreads();
    }
    if (t < NB_SCAN) g_bsum[t] = s[t] - v;  // exclusive
}

__global__ void scan3_kernel() {            // local scan + block offset
    __shared__ int s[256];
    int t = threadIdx.x;
    int i = blockIdx.x * 256 + t;
    int v = (i < N_NODES) ? g_cnt[i] : 0;
    s[t] = v;
    __syncthreads();
    for (int d = 1; d < 256; d <<= 1) {
        int u = (t >= d) ? s[t - d] : 0;
        __syncthreads();
        s[t] += u;
        __syncthreads();
    }
    int base = g_bsum[blockIdx.x];
    if (i < N_NODES) g_off[i] = base + s[t] - v;
    if (i == N_NODES - 1) g_off[N_NODES] = base + s[t];
}

// -------- fill CSR: sorted-by-target src ids + precomputed norms --------
__global__ void fill_kernel(const int* __restrict__ ei,
                            const float* __restrict__ ew) {
    int e = blockIdx.x * blockDim.x + threadIdx.x;
    if (e >= N_EDGES) return;
    int r = ei[e];
    int c = ei[N_EDGES + e];
    int pos = g_off[c] + atomicAdd(&g_cur[c], 1);
    g_src[pos] = r;
    g_nrm[pos] = g_dinv[r] * ew[e] * g_dinv[c];
}

// -------- GEMM: Y[50000,128] = X[50000,128] @ W[128,128], fp32 --------
// block = 256 threads, tile = 32 rows x 128 cols, 4x4 outputs per thread.
// Xt stored k-major-transposed so A operand is a single LDS.128 broadcast.
__global__ __launch_bounds__(256) void gemm_kernel(const float* __restrict__ Xext,
                                                   const float* __restrict__ W,
                                                   int srcSel) {
    __shared__ float Wsh[128 * 128];   // [k][n]
    __shared__ float Xt [128 * 32];    // [k][m]
    const float* X = (srcSel == 0) ? Xext : g_bufB;
    float* Y = g_bufA;

    const int t = threadIdx.x;
    const int rowBase = blockIdx.x * 32;

    // W direct copy (already [k][n] row-major)
    const float4* W4 = reinterpret_cast<const float4*>(W);
    float4* Wsh4 = reinterpret_cast<float4*>(Wsh);
#pragma unroll
    for (int i = 0; i < 16; i++) Wsh4[t + 256 * i] = W4[t + 256 * i];

    // X tile: load row-major float4, store transposed scalars
    const float4* X4 = reinterpret_cast<const float4*>(X);
#pragma unroll
    for (int i = 0; i < 4; i++) {
        int q  = t + 256 * i;            // 0..1023
        int r  = q >> 5;                 // 0..31 local row
        int kf = q & 31;                 // float4 index along k
        int rg = rowBase + r;
        if (rg >= N_NODES) rg = N_NODES - 1;   // clamp (values discarded)
        float4 v = X4[rg * 32 + kf];
        Xt[(kf * 4 + 0) * 32 + r] = v.x;
        Xt[(kf * 4 + 1) * 32 + r] = v.y;
        Xt[(kf * 4 + 2) * 32 + r] = v.z;
        Xt[(kf * 4 + 3) * 32 + r] = v.w;
    }
    __syncthreads();

    const int tx = t & 31;   // col group: cols tx*4..tx*4+3
    const int ty = t >> 5;   // row group: rows ty*4..ty*4+3
    float4 acc0 = make_float4(0.f,0.f,0.f,0.f);
    float4 acc1 = make_float4(0.f,0.f,0.f,0.f);
    float4 acc2 = make_float4(0.f,0.f,0.f,0.f);
    float4 acc3 = make_float4(0.f,0.f,0.f,0.f);

#pragma unroll 8
    for (int k = 0; k < 128; k++) {
        float4 a = *reinterpret_cast<const float4*>(&Xt[k * 32 + ty * 4]);
        float4 w = *reinterpret_cast<const float4*>(&Wsh[k * 128 + tx * 4]);
        acc0.x = fmaf(a.x, w.x, acc0.x); acc0.y = fmaf(a.x, w.y, acc0.y);
        acc0.z = fmaf(a.x, w.z, acc0.z); acc0.w = fmaf(a.x, w.w, acc0.w);
        acc1.x = fmaf(a.y, w.x, acc1.x); acc1.y = fmaf(a.y, w.y, acc1.y);
        acc1.z = fmaf(a.y, w.z, acc1.z); acc1.w = fmaf(a.y, w.w, acc1.w);
        acc2.x = fmaf(a.z, w.x, acc2.x); acc2.y = fmaf(a.z, w.y, acc2.y);
        acc2.z = fmaf(a.z, w.z, acc2.z); acc2.w = fmaf(a.z, w.w, acc2.w);
        acc3.x = fmaf(a.w, w.x, acc3.x); acc3.y = fmaf(a.w, w.y, acc3.y);
        acc3.z = fmaf(a.w, w.z, acc3.z); acc3.w = fmaf(a.w, w.w, acc3.w);
    }

    float4* Y4 = reinterpret_cast<float4*>(Y);
    int r0 = rowBase + ty * 4;
    if (r0 + 0 < N_NODES) Y4[(r0 + 0) * 32 + tx] = acc0;
    if (r0 + 1 < N_NODES) Y4[(r0 + 1) * 32 + tx] = acc1;
    if (r0 + 2 < N_NODES) Y4[(r0 + 2) * 32 + tx] = acc2;
    if (r0 + 3 < N_NODES) Y4[(r0 + 3) * 32 + tx] = acc3;
}

#define AGG_EDGE(S, WGT)                                            \
    {   float4 v = in4[(S) * 32 + lane];                            \
        acc.x = fmaf((WGT), v.x, acc.x);                            \
        acc.y = fmaf((WGT), v.y, acc.y);                            \
        acc.z = fmaf((WGT), v.z, acc.z);                            \
        acc.w = fmaf((WGT), v.w, acc.w); }

// -------- aggregation: warp per node; reads g_bufA --------
// out = relu( sum_{in-edges} nrm_e * A[src_e] + dinv^2 * A[node] + bias )
template <bool POOL>
__global__ __launch_bounds__(256) void agg_kernel(const float* __restrict__ bias,
                                                  const int* __restrict__ batch) {
    const int node = blockIdx.x * 8 + (threadIdx.x >> 5);
    const int lane = threadIdx.x & 31;
    const float4* in4 = reinterpret_cast<const float4*>(g_bufA);

    float di = g_dinv[node];
    float s2 = di * di;
    float4 a = in4[node * 32 + lane];
    float4 acc = make_float4(s2 * a.x, s2 * a.y, s2 * a.z, s2 * a.w);

    int e  = g_off[node];
    int e1 = g_off[node + 1];
    for (; e + 3 < e1; e += 4) {
        int   s0 = g_src[e],   s1 = g_src[e+1], s2i = g_src[e+2], s3 = g_src[e+3];
        float w0 = g_nrm[e],   w1 = g_nrm[e+1], w2  = g_nrm[e+2], w3 = g_nrm[e+3];
        float4 v0 = in4[s0 * 32 + lane];
        float4 v1 = in4[s1 * 32 + lane];
        float4 v2 = in4[s2i * 32 + lane];
        float4 v3 = in4[s3 * 32 + lane];
        acc.x = fmaf(w0, v0.x, acc.x); acc.y = fmaf(w0, v0.y, acc.y);
        acc.z = fmaf(w0, v0.z, acc.z); acc.w = fmaf(w0, v0.w, acc.w);
        acc.x = fmaf(w1, v1.x, acc.x); acc.y = fmaf(w1, v1.y, acc.y);
        acc.z = fmaf(w1, v1.z, acc.z); acc.w = fmaf(w1, v1.w, acc.w);
        acc.x = fmaf(w2, v2.x, acc.x); acc.y = fmaf(w2, v2.y, acc.y);
        acc.z = fmaf(w2, v2.z, acc.z); acc.w = fmaf(w2, v2.w, acc.w);
        acc.x = fmaf(w3, v3.x, acc.x); acc.y = fmaf(w3, v3.y, acc.y);
        acc.z = fmaf(w3, v3.z, acc.z); acc.w = fmaf(w3, v3.w, acc.w);
    }
    for (; e < e1; e++) {
        int s0 = g_src[e]; float w0 = g_nrm[e];
        AGG_EDGE(s0, w0);
    }

    float4 b = reinterpret_cast<const float4*>(bias)[lane];
    acc.x = fmaxf(acc.x + b.x, 0.f);
    acc.y = fmaxf(acc.y + b.y, 0.f);
    acc.z = fmaxf(acc.z + b.z, 0.f);
    acc.w = fmaxf(acc.w + b.w, 0.f);

    if (POOL) {
        int g = batch[node];
        float* p = &g_pool[g * D + lane * 4];
        atomicAdd(p + 0, acc.x);
        atomicAdd(p + 1, acc.y);
        atomicAdd(p + 2, acc.z);
        atomicAdd(p + 3, acc.w);
    } else {
        reinterpret_cast<float4*>(g_bufB)[node * 32 + lane] = acc;
    }
}

// -------- head: out[g] = (pool[g]/count) . Wh + bh --------
__global__ void final_kernel(const float* __restrict__ Wh,
                             const float* __restrict__ bh,
                             float* __restrict__ out) {
    __shared__ float red[128];
    const int g = blockIdx.x;
    const int t = threadIdx.x;
    float c = (float)g_gcnt[g];
    c = fmaxf(c, 1.0f);
    float v = (g_pool[g * D + t] / c) * Wh[t];
    red[t] = v;
    __syncthreads();
    for (int s = 64; s > 0; s >>= 1) {
        if (t < s) red[t] += red[t + s];
        __syncthreads();
    }
    if (t == 0) out[g] = red[0] + bh[0];
}

extern "C" void kernel_launch(void* const* d_in, const int* in_sizes, int n_in,
                              void* d_out, int out_size) {
    const float* x     = (const float*)d_in[0];
    const float* ew    = (const float*)d_in[1];
    const float* W1    = (const float*)d_in[2];
    const float* b1    = (const float*)d_in[3];
    const float* W2    = (const float*)d_in[4];
    const float* b2    = (const float*)d_in[5];
    const float* Wh    = (const float*)d_in[6];
    const float* bh    = (const float*)d_in[7];
    const int*   ei    = (const int*)d_in[8];
    const int*   batch = (const int*)d_in[9];
    float*       out   = (float*)d_out;

    const int NB_N = (N_NODES + 255) / 256;   // 196
    const int NB_E = (N_EDGES + 255) / 256;   // 3125

    init_kernel<<<NB_N, 256>>>();
    edge_deg_kernel<<<NB_E, 256>>>(ei, ew);
    dinv_kernel<<<NB_N, 256>>>(batch);
    scan1_kernel<<<NB_SCAN, 256>>>();
    scan2_kernel<<<1, 256>>>();
    scan3_kernel<<<NB_SCAN, 256>>>();
    fill_kernel<<<NB_E, 256>>>(ei, ew);

    // layer 1: A = x @ W1 ; B = relu(agg(A) + b1)
    gemm_kernel<<<(N_NODES + 31) / 32, 256>>>(x, W1, 0);
    agg_kernel<false><<<N_NODES / 8, 256>>>(b1, batch);

    // layer 2: A = B @ W2 ; pooled += relu(agg(A) + b2)
    gemm_kernel<<<(N_NODES + 31) / 32, 256>>>(nullptr, W2, 1);
    agg_kernel<true><<<N_NODES / 8, 256>>>(b2, batch);

    final_kernel<<<N_GR, 128>>>(Wh, bh, out);
}

// round 5
// speedup vs baseline: 1.7592x; 1.3047x over previous
#include <cuda_runtime.h>
#include <cstdint>

#define N_NODES 50000
#define N_EDGES 800000
#define D       128
#define N_GR    64
#define NB_SCAN 196   // ceil(50000/256)

// -------- device scratch (no allocations allowed) --------
__device__ float g_deg [N_NODES];
__device__ float g_dinv[N_NODES];
__device__ int   g_cnt [N_NODES];
__device__ int   g_cur [N_NODES];
__device__ int   g_off [N_NODES + 1];
__device__ int   g_bsum[256];
__device__ int   g_src [N_EDGES];
__device__ float g_nrm [N_EDGES];
__device__ float g_bufA[N_NODES * D];   // GEMM output (pre-aggregation features)
__device__ float g_bufB[N_NODES * D];   // aggregated + relu features (h1)
__device__ float g_pool[N_GR * D];
__device__ int   g_gcnt[N_GR];
__device__ float g_wr1[128 * 128];      // tf32-rounded W1 ([k][n])
__device__ float g_wr2[128 * 128];      // tf32-rounded W2 ([k][n])

// ---------------- helpers ----------------
__device__ __forceinline__ float tf32r(float x) {
    uint32_t u;
    asm("cvt.rna.tf32.f32 %0, %1;" : "=r"(u) : "f"(x));
    return __uint_as_float(u);
}

__device__ __forceinline__ void mma_tf32(float* c, const uint32_t* a, const uint32_t* b) {
    asm volatile("mma.sync.aligned.m16n8k8.row.col.f32.tf32.tf32.f32 "
                 "{%0,%1,%2,%3}, {%4,%5,%6,%7}, {%8,%9}, {%0,%1,%2,%3};"
                 : "+f"(c[0]), "+f"(c[1]), "+f"(c[2]), "+f"(c[3])
                 : "r"(a[0]), "r"(a[1]), "r"(a[2]), "r"(a[3]),
                   "r"(b[0]), "r"(b[1]));
}

// -------- init accumulators (runs every replay) --------
__global__ void init_kernel() {
    int i = blockIdx.x * blockDim.x + threadIdx.x;
    if (i < N_NODES) { g_deg[i] = 1.0f; g_cnt[i] = 0; g_cur[i] = 0; }
    if (i < N_GR * D) g_pool[i] = 0.0f;
    if (i < N_GR)     g_gcnt[i] = 0;
}

// -------- tf32-round the weight matrices (once per call) --------
__global__ void wimg_kernel(const float* __restrict__ W1,
                            const float* __restrict__ W2) {
    int q = blockIdx.x * 256 + threadIdx.x;    // 0..16383
    g_wr1[q] = tf32r(W1[q]);
    g_wr2[q] = tf32r(W2[q]);
}

// -------- per-edge: degree sum + in-degree count --------
__global__ void edge_deg_kernel(const int* __restrict__ ei,
                                const float* __restrict__ ew) {
    int e = blockIdx.x * blockDim.x + threadIdx.x;
    if (e >= N_EDGES) return;
    int c = ei[N_EDGES + e];          // target node
    atomicAdd(&g_deg[c], ew[e]);
    atomicAdd(&g_cnt[c], 1);
}

// -------- per-node: dinv = rsqrt(deg), graph node counts --------
__global__ void dinv_kernel(const int* __restrict__ batch) {
    int i = blockIdx.x * blockDim.x + threadIdx.x;
    if (i >= N_NODES) return;
    g_dinv[i] = rsqrtf(g_deg[i]);
    atomicAdd(&g_gcnt[batch[i]], 1);
}

// -------- 3-pass parallel exclusive scan over g_cnt -> g_off --------
__global__ void scan1_kernel() {
    __shared__ int s[256];
    int t = threadIdx.x;
    int i = blockIdx.x * 256 + t;
    int v = (i < N_NODES) ? g_cnt[i] : 0;
    s[t] = v;
    __syncthreads();
    for (int d = 128; d > 0; d >>= 1) {
        if (t < d) s[t] += s[t + d];
        __syncthreads();
    }
    if (t == 0) g_bsum[blockIdx.x] = s[0];
}

__global__ void scan2_kernel() {
    __shared__ int s[256];
    int t = threadIdx.x;
    int v = (t < NB_SCAN) ? g_bsum[t] : 0;
    s[t] = v;
    __syncthreads();
    for (int d = 1; d < 256; d <<= 1) {
        int u = (t >= d) ? s[t - d] : 0;
        __syncthreads();
        s[t] += u;
        __syncthreads();
    }
    if (t < NB_SCAN) g_bsum[t] = s[t] - v;
}

__global__ void scan3_kernel() {
    __shared__ int s[256];
    int t = threadIdx.x;
    int i = blockIdx.x * 256 + t;
    int v = (i < N_NODES) ? g_cnt[i] : 0;
    s[t] = v;
    __syncthreads();
    for (int d = 1; d < 256; d <<= 1) {
        int u = (t >= d) ? s[t - d] : 0;
        __syncthreads();
        s[t] += u;
        __syncthreads();
    }
    int base = g_bsum[blockIdx.x];
    if (i < N_NODES) g_off[i] = base + s[t] - v;
    if (i == N_NODES - 1) g_off[N_NODES] = base + s[t];
}

// -------- fill CSR --------
__global__ void fill_kernel(const int* __restrict__ ei,
                            const float* __restrict__ ew) {
    int e = blockIdx.x * blockDim.x + threadIdx.x;
    if (e >= N_EDGES) return;
    int r = ei[e];
    int c = ei[N_EDGES + e];
    int pos = g_off[c] + atomicAdd(&g_cur[c], 1);
    g_src[pos] = r;
    g_nrm[pos] = g_dinv[r] * ew[e] * g_dinv[c];
}

// -------- tf32 mma.sync GEMM: Y[128-tile,128] = X-tile @ W --------
// 256 threads, 8 warps; warp tile 32x64 (2 m-frags x 8 n-frags of m16n8k8).
// Smem stride 132 floats -> fragment loads are bank-conflict-free.
#define XS_STRIDE 132
#define GEMM_SMEM_BYTES (2 * 128 * XS_STRIDE * 4)

__global__ __launch_bounds__(256) void gemm_mma(const float* __restrict__ Xext,
                                                int which) {
    extern __shared__ float sh[];
    float* Xs = sh;                       // [128][132]
    float* Ws = sh + 128 * XS_STRIDE;     // [128][132]  (W[k][n])

    const float* X  = which ? g_bufB : Xext;
    const float* Wr = which ? g_wr2 : g_wr1;

    const int tid = threadIdx.x;
    const int rowBase = blockIdx.x * 128;

    // X tile: load float4, tf32-round, store padded
    const float4* X4 = reinterpret_cast<const float4*>(X);
#pragma unroll
    for (int i = 0; i < 16; i++) {
        int q = tid + 256 * i;            // 0..4095
        int r = q >> 5, c4 = q & 31;
        int rg = rowBase + r; if (rg >= N_NODES) rg = N_NODES - 1;
        float4 v = X4[rg * 32 + c4];
        float* d = &Xs[r * XS_STRIDE + c4 * 4];
        d[0] = tf32r(v.x); d[1] = tf32r(v.y); d[2] = tf32r(v.z); d[3] = tf32r(v.w);
    }
    // W: already rounded, straight copy into padded layout
    const float4* W4 = reinterpret_cast<const float4*>(Wr);
#pragma unroll
    for (int i = 0; i < 16; i++) {
        int q = tid + 256 * i;
        int r = q >> 5, c4 = q & 31;
        *reinterpret_cast<float4*>(&Ws[r * XS_STRIDE + c4 * 4]) = W4[q];
    }
    __syncthreads();

    const int lane = tid & 31, wid = tid >> 5;
    const int g = lane >> 2, t = lane & 3;
    const int mw = (wid >> 1) * 32;       // warp row offset in tile
    const int nw = (wid & 1) * 64;        // warp col offset

    float c[2][8][4];
#pragma unroll
    for (int mt = 0; mt < 2; mt++)
#pragma unroll
        for (int nt = 0; nt < 8; nt++)
#pragma unroll
            for (int j = 0; j < 4; j++) c[mt][nt][j] = 0.f;

#pragma unroll 4
    for (int k0 = 0; k0 < 128; k0 += 8) {
        uint32_t a[2][4], b[8][2];
#pragma unroll
        for (int mt = 0; mt < 2; mt++) {
            const float* base = &Xs[(mw + mt * 16 + g) * XS_STRIDE + k0 + t];
            a[mt][0] = __float_as_uint(base[0]);
            a[mt][1] = __float_as_uint(base[8 * XS_STRIDE]);
            a[mt][2] = __float_as_uint(base[4]);
            a[mt][3] = __float_as_uint(base[8 * XS_STRIDE + 4]);
        }
#pragma unroll
        for (int nt = 0; nt < 8; nt++) {
            const float* bb = &Ws[(k0 + t) * XS_STRIDE + nw + nt * 8 + g];
            b[nt][0] = __float_as_uint(bb[0]);
            b[nt][1] = __float_as_uint(bb[4 * XS_STRIDE]);
        }
#pragma unroll
        for (int mt = 0; mt < 2; mt++)
#pragma unroll
            for (int nt = 0; nt < 8; nt++)
                mma_tf32(c[mt][nt], a[mt], b[nt]);
    }

    // epilogue: c0,c1 at (row, 2t), c2,c3 at (row+8, 2t)
    float2* Y2 = reinterpret_cast<float2*>(g_bufA);
#pragma unroll
    for (int mt = 0; mt < 2; mt++) {
        int row = rowBase + mw + mt * 16 + g;
#pragma unroll
        for (int nt = 0; nt < 8; nt++) {
            int col = nw + nt * 8 + 2 * t;
            if (row < N_NODES)
                Y2[row * 64 + (col >> 1)] = make_float2(c[mt][nt][0], c[mt][nt][1]);
            if (row + 8 < N_NODES)
                Y2[(row + 8) * 64 + (col >> 1)] = make_float2(c[mt][nt][2], c[mt][nt][3]);
        }
    }
}

// -------- aggregation: warp per node; reads g_bufA --------
template <bool POOL>
__global__ __launch_bounds__(256) void agg_kernel(const float* __restrict__ bias,
                                                  const int* __restrict__ batch) {
    const int node = blockIdx.x * 8 + (threadIdx.x >> 5);
    const int lane = threadIdx.x & 31;
    const float4* in4 = reinterpret_cast<const float4*>(g_bufA);

    float di = g_dinv[node];
    float s2 = di * di;
    float4 a = in4[node * 32 + lane];
    float4 acc = make_float4(s2 * a.x, s2 * a.y, s2 * a.z, s2 * a.w);

    int e  = g_off[node];
    int e1 = g_off[node + 1];
    for (; e + 3 < e1; e += 4) {
        int   s0 = g_src[e],   s1 = g_src[e+1], s2i = g_src[e+2], s3 = g_src[e+3];
        float w0 = g_nrm[e],   w1 = g_nrm[e+1], w2  = g_nrm[e+2], w3 = g_nrm[e+3];
        float4 v0 = in4[s0 * 32 + lane];
        float4 v1 = in4[s1 * 32 + lane];
        float4 v2 = in4[s2i * 32 + lane];
        float4 v3 = in4[s3 * 32 + lane];
        acc.x = fmaf(w0, v0.x, acc.x); acc.y = fmaf(w0, v0.y, acc.y);
        acc.z = fmaf(w0, v0.z, acc.z); acc.w = fmaf(w0, v0.w, acc.w);
        acc.x = fmaf(w1, v1.x, acc.x); acc.y = fmaf(w1, v1.y, acc.y);
        acc.z = fmaf(w1, v1.z, acc.z); acc.w = fmaf(w1, v1.w, acc.w);
        acc.x = fmaf(w2, v2.x, acc.x); acc.y = fmaf(w2, v2.y, acc.y);
        acc.z = fmaf(w2, v2.z, acc.z); acc.w = fmaf(w2, v2.w, acc.w);
        acc.x = fmaf(w3, v3.x, acc.x); acc.y = fmaf(w3, v3.y, acc.y);
        acc.z = fmaf(w3, v3.z, acc.z); acc.w = fmaf(w3, v3.w, acc.w);
    }
    for (; e < e1; e++) {
        int s0 = g_src[e]; float w0 = g_nrm[e];
        float4 v = in4[s0 * 32 + lane];
        acc.x = fmaf(w0, v.x, acc.x); acc.y = fmaf(w0, v.y, acc.y);
        acc.z = fmaf(w0, v.z, acc.z); acc.w = fmaf(w0, v.w, acc.w);
    }

    float4 b = reinterpret_cast<const float4*>(bias)[lane];
    acc.x = fmaxf(acc.x + b.x, 0.f);
    acc.y = fmaxf(acc.y + b.y, 0.f);
    acc.z = fmaxf(acc.z + b.z, 0.f);
    acc.w = fmaxf(acc.w + b.w, 0.f);

    if (POOL) {
        int g = batch[node];
        float* p = &g_pool[g * D + lane * 4];
        atomicAdd(p + 0, acc.x);
        atomicAdd(p + 1, acc.y);
        atomicAdd(p + 2, acc.z);
        atomicAdd(p + 3, acc.w);
    } else {
        reinterpret_cast<float4*>(g_bufB)[node * 32 + lane] = acc;
    }
}

// -------- head: out[g] = (pool[g]/count) . Wh + bh --------
__global__ void final_kernel(const float* __restrict__ Wh,
                             const float* __restrict__ bh,
                             float* __restrict__ out) {
    __shared__ float red[128];
    const int g = blockIdx.x;
    const int t = threadIdx.x;
    float c = (float)g_gcnt[g];
    c = fmaxf(c, 1.0f);
    float v = (g_pool[g * D + t] / c) * Wh[t];
    red[t] = v;
    __syncthreads();
    for (int s = 64; s > 0; s >>= 1) {
        if (t < s) red[t] += red[t + s];
        __syncthreads();
    }
    if (t == 0) out[g] = red[0] + bh[0];
}

extern "C" void kernel_launch(void* const* d_in, const int* in_sizes, int n_in,
                              void* d_out, int out_size) {
    const float* x     = (const float*)d_in[0];
    const float* ew    = (const float*)d_in[1];
    const float* W1    = (const float*)d_in[2];
    const float* b1    = (const float*)d_in[3];
    const float* W2    = (const float*)d_in[4];
    const float* b2    = (const float*)d_in[5];
    const float* Wh    = (const float*)d_in[6];
    const float* bh    = (const float*)d_in[7];
    const int*   ei    = (const int*)d_in[8];
    const int*   batch = (const int*)d_in[9];
    float*       out   = (float*)d_out;

    const int NB_N = (N_NODES + 255) / 256;   // 196
    const int NB_E = (N_EDGES + 255) / 256;   // 3125
    const int NB_G = (N_NODES + 127) / 128;   // 391

    static bool attr_set = false;
    if (!attr_set) {
        cudaFuncSetAttribute(gemm_mma, cudaFuncAttributeMaxDynamicSharedMemorySize,
                             GEMM_SMEM_BYTES);
        attr_set = true;
    }

    init_kernel<<<NB_N, 256>>>();
    wimg_kernel<<<64, 256>>>(W1, W2);
    edge_deg_kernel<<<NB_E, 256>>>(ei, ew);
    gemm_mma<<<NB_G, 256, GEMM_SMEM_BYTES>>>(x, 0);        // layer-1 GEMM
    dinv_kernel<<<NB_N, 256>>>(batch);
    scan1_kernel<<<NB_SCAN, 256>>>();
    scan2_kernel<<<1, 256>>>();
    scan3_kernel<<<NB_SCAN, 256>>>();
    fill_kernel<<<NB_E, 256>>>(ei, ew);

    agg_kernel<false><<<N_NODES / 8, 256>>>(b1, batch);
    gemm_mma<<<NB_G, 256, GEMM_SMEM_BYTES>>>(nullptr, 1);  // layer-2 GEMM
    agg_kernel<true><<<N_NODES / 8, 256>>>(b2, batch);

    final_kernel<<<N_GR, 128>>>(Wh, bh, out);
}

// round 6
// speedup vs baseline: 1.8451x; 1.0489x over previous
#include <cuda_runtime.h>
#include <cuda_bf16.h>
#include <cstdint>

#define N_NODES 50000
#define N_EDGES 800000
#define D       128
#define N_GR    64
#define NB_SCAN 196   // ceil(50000/256)

// -------- device scratch (no allocations allowed) --------
__device__ float    g_deg [N_NODES];
__device__ float    g_dinv[N_NODES];
__device__ int      g_cnt [N_NODES];
__device__ int      g_cur [N_NODES];
__device__ int      g_off [N_NODES + 1];
__device__ int      g_bsum[256];
__device__ uint2    g_edge[N_EDGES];        // {src, norm-bits} per CSR slot
__device__ uint32_t g_bufA[N_NODES * 64];   // GEMM output, bf16x2-packed (gathered)
__device__ float    g_bufB[N_NODES * D];    // h1, fp32 (read sequentially by GEMM2)
__device__ float    g_pool[N_GR * D];
__device__ int      g_gcnt[N_GR];
__device__ float    g_wr1[128 * 128];       // tf32-rounded W1 ([k][n])
__device__ float    g_wr2[128 * 128];       // tf32-rounded W2 ([k][n])

// ---------------- helpers ----------------
__device__ __forceinline__ float tf32r(float x) {
    uint32_t u;
    asm("cvt.rna.tf32.f32 %0, %1;" : "=r"(u) : "f"(x));
    return __uint_as_float(u);
}

__device__ __forceinline__ uint32_t packbf(float x, float y) {
    __nv_bfloat162 h = __floats2bfloat162_rn(x, y);
    return *reinterpret_cast<uint32_t*>(&h);
}

__device__ __forceinline__ float4 u2f4(uint2 u) {
    __nv_bfloat162 lo = *reinterpret_cast<__nv_bfloat162*>(&u.x);
    __nv_bfloat162 hi = *reinterpret_cast<__nv_bfloat162*>(&u.y);
    float2 a = __bfloat1622float2(lo);
    float2 b = __bfloat1622float2(hi);
    return make_float4(a.x, a.y, b.x, b.y);
}

__device__ __forceinline__ void mma_tf32(float* c, const uint32_t* a, const uint32_t* b) {
    asm volatile("mma.sync.aligned.m16n8k8.row.col.f32.tf32.tf32.f32 "
                 "{%0,%1,%2,%3}, {%4,%5,%6,%7}, {%8,%9}, {%0,%1,%2,%3};"
                 : "+f"(c[0]), "+f"(c[1]), "+f"(c[2]), "+f"(c[3])
                 : "r"(a[0]), "r"(a[1]), "r"(a[2]), "r"(a[3]),
                   "r"(b[0]), "r"(b[1]));
}

// -------- init accumulators + tf32-round weights (runs every replay) --------
__global__ void init_kernel(const float* __restrict__ W1,
                            const float* __restrict__ W2) {
    int i = blockIdx.x * blockDim.x + threadIdx.x;
    if (i < N_NODES) { g_deg[i] = 1.0f; g_cnt[i] = 0; g_cur[i] = 0; }
    if (i < 128 * 128) { g_wr1[i] = tf32r(W1[i]); g_wr2[i] = tf32r(W2[i]); }
    if (i < N_GR * D) g_pool[i] = 0.0f;
    if (i < N_GR)     g_gcnt[i] = 0;
}

// -------- per-edge: degree sum + in-degree count --------
__global__ void edge_deg_kernel(const int* __restrict__ ei,
                                const float* __restrict__ ew) {
    int e = blockIdx.x * blockDim.x + threadIdx.x;
    if (e >= N_EDGES) return;
    int c = ei[N_EDGES + e];          // target node
    atomicAdd(&g_deg[c], ew[e]);
    atomicAdd(&g_cnt[c], 1);
}

// -------- per-node: dinv = rsqrt(deg), graph node counts --------
__global__ void dinv_kernel(const int* __restrict__ batch) {
    int i = blockIdx.x * blockDim.x + threadIdx.x;
    if (i >= N_NODES) return;
    g_dinv[i] = rsqrtf(g_deg[i]);
    atomicAdd(&g_gcnt[batch[i]], 1);
}

// -------- 3-pass parallel exclusive scan over g_cnt -> g_off --------
__global__ void scan1_kernel() {
    __shared__ int s[256];
    int t = threadIdx.x;
    int i = blockIdx.x * 256 + t;
    int v = (i < N_NODES) ? g_cnt[i] : 0;
    s[t] = v;
    __syncthreads();
    for (int d = 128; d > 0; d >>= 1) {
        if (t < d) s[t] += s[t + d];
        __syncthreads();
    }
    if (t == 0) g_bsum[blockIdx.x] = s[0];
}

__global__ void scan2_kernel() {
    __shared__ int s[256];
    int t = threadIdx.x;
    int v = (t < NB_SCAN) ? g_bsum[t] : 0;
    s[t] = v;
    __syncthreads();
    for (int d = 1; d < 256; d <<= 1) {
        int u = (t >= d) ? s[t - d] : 0;
        __syncthreads();
        s[t] += u;
        __syncthreads();
    }
    if (t < NB_SCAN) g_bsum[t] = s[t] - v;
}

__global__ void scan3_kernel() {
    __shared__ int s[256];
    int t = threadIdx.x;
    int i = blockIdx.x * 256 + t;
    int v = (i < N_NODES) ? g_cnt[i] : 0;
    s[t] = v;
    __syncthreads();
    for (int d = 1; d < 256; d <<= 1) {
        int u = (t >= d) ? s[t - d] : 0;
        __syncthreads();
        s[t] += u;
        __syncthreads();
    }
    int base = g_bsum[blockIdx.x];
    if (i < N_NODES) g_off[i] = base + s[t] - v;
    if (i == N_NODES - 1) g_off[N_NODES] = base + s[t];
}

// -------- fill CSR: fused {src, norm} records --------
__global__ void fill_kernel(const int* __restrict__ ei,
                            const float* __restrict__ ew) {
    int e = blockIdx.x * blockDim.x + threadIdx.x;
    if (e >= N_EDGES) return;
    int r = ei[e];
    int c = ei[N_EDGES + e];
    int pos = g_off[c] + atomicAdd(&g_cur[c], 1);
    float nrm = g_dinv[r] * ew[e] * g_dinv[c];
    g_edge[pos] = make_uint2((uint32_t)r, __float_as_uint(nrm));
}

// -------- tf32 mma.sync GEMM: g_bufA(bf16)[64-tile,128] = X-tile @ W --------
// 256 threads, 8 warps (2x4); warp tile 32x32 (2 m-frags x 4 n-frags m16n8k8).
// smem 99KB -> 2 blocks/SM for memory/compute overlap across blocks.
#define BM 64
#define XS_STRIDE 132
#define GEMM_SMEM_BYTES ((BM + 128) * XS_STRIDE * 4)

__global__ __launch_bounds__(256, 2) void gemm_mma(const float* __restrict__ Xext,
                                                   int which) {
    extern __shared__ float sh[];
    float* Xs = sh;                       // [64][132]
    float* Ws = sh + BM * XS_STRIDE;      // [128][132]  (W[k][n])

    const float* X  = which ? g_bufB : Xext;
    const float* Wr = which ? g_wr2 : g_wr1;

    const int tid = threadIdx.x;
    const int rowBase = blockIdx.x * BM;

    // X tile: load float4, tf32-round, store padded
    const float4* X4 = reinterpret_cast<const float4*>(X);
#pragma unroll
    for (int i = 0; i < 8; i++) {
        int q = tid + 256 * i;            // 0..2047
        int r = q >> 5, c4 = q & 31;
        int rg = rowBase + r; if (rg >= N_NODES) rg = N_NODES - 1;
        float4 v = X4[rg * 32 + c4];
        float* d = &Xs[r * XS_STRIDE + c4 * 4];
        d[0] = tf32r(v.x); d[1] = tf32r(v.y); d[2] = tf32r(v.z); d[3] = tf32r(v.w);
    }
    // W: already rounded, straight copy into padded layout
    const float4* W4 = reinterpret_cast<const float4*>(Wr);
#pragma unroll
    for (int i = 0; i < 16; i++) {
        int q = tid + 256 * i;            // 0..4095
        int r = q >> 5, c4 = q & 31;
        *reinterpret_cast<float4*>(&Ws[r * XS_STRIDE + c4 * 4]) = W4[q];
    }
    __syncthreads();

    const int lane = tid & 31, wid = tid >> 5;
    const int g = lane >> 2, t = lane & 3;
    const int mw = (wid >> 2) * 32;       // warp row offset (0/32)
    const int nw = (wid & 3) * 32;        // warp col offset (0/32/64/96)

    float c[2][4][4];
#pragma unroll
    for (int mt = 0; mt < 2; mt++)
#pragma unroll
        for (int nt = 0; nt < 4; nt++)
#pragma unroll
            for (int j = 0; j < 4; j++) c[mt][nt][j] = 0.f;

#pragma unroll 4
    for (int k0 = 0; k0 < 128; k0 += 8) {
        uint32_t a[2][4], b[4][2];
#pragma unroll
        for (int mt = 0; mt < 2; mt++) {
            const float* base = &Xs[(mw + mt * 16 + g) * XS_STRIDE + k0 + t];
            a[mt][0] = __float_as_uint(base[0]);
            a[mt][1] = __float_as_uint(base[8 * XS_STRIDE]);
            a[mt][2] = __float_as_uint(base[4]);
            a[mt][3] = __float_as_uint(base[8 * XS_STRIDE + 4]);
        }
#pragma unroll
        for (int nt = 0; nt < 4; nt++) {
            const float* bb = &Ws[(k0 + t) * XS_STRIDE + nw + nt * 8 + g];
            b[nt][0] = __float_as_uint(bb[0]);
            b[nt][1] = __float_as_uint(bb[4 * XS_STRIDE]);
        }
#pragma unroll
        for (int mt = 0; mt < 2; mt++)
#pragma unroll
            for (int nt = 0; nt < 4; nt++)
                mma_tf32(c[mt][nt], a[mt], b[nt]);
    }

    // epilogue: pack pairs (cols 2t,2t+1) to bf16x2
#pragma unroll
    for (int mt = 0; mt < 2; mt++) {
        int row = rowBase + mw + mt * 16 + g;
#pragma unroll
        for (int nt = 0; nt < 4; nt++) {
            int ci = ((nw + nt * 8) >> 1) + t;      // bf16x2 column index
            if (row < N_NODES)
                g_bufA[row * 64 + ci] = packbf(c[mt][nt][0], c[mt][nt][1]);
            if (row + 8 < N_NODES)
                g_bufA[(row + 8) * 64 + ci] = packbf(c[mt][nt][2], c[mt][nt][3]);
        }
    }
}

// -------- aggregation: warp per node; gathers bf16 rows from g_bufA --------
// out = relu( sum_{in-edges} nrm_e * A[src_e] + dinv^2 * A[node] + bias )
template <bool POOL>
__global__ __launch_bounds__(256) void agg_kernel(const float* __restrict__ bias,
                                                  const int* __restrict__ batch) {
    const int node = blockIdx.x * 8 + (threadIdx.x >> 5);
    const int lane = threadIdx.x & 31;
    const uint2* in2 = reinterpret_cast<const uint2*>(g_bufA);

    float di = g_dinv[node];
    float s2 = di * di;
    float4 av = u2f4(in2[node * 32 + lane]);
    float4 acc = make_float4(s2 * av.x, s2 * av.y, s2 * av.z, s2 * av.w);

    int e  = g_off[node];
    int e1 = g_off[node + 1];
    for (; e + 3 < e1; e += 4) {
        uint2 m0 = g_edge[e],   m1 = g_edge[e+1];
        uint2 m2 = g_edge[e+2], m3 = g_edge[e+3];
        uint2 r0 = in2[m0.x * 32 + lane];
        uint2 r1 = in2[m1.x * 32 + lane];
        uint2 r2 = in2[m2.x * 32 + lane];
        uint2 r3 = in2[m3.x * 32 + lane];
        float w0 = __uint_as_float(m0.y), w1 = __uint_as_float(m1.y);
        float w2 = __uint_as_float(m2.y), w3 = __uint_as_float(m3.y);
        float4 v0 = u2f4(r0), v1 = u2f4(r1), v2 = u2f4(r2), v3 = u2f4(r3);
        acc.x = fmaf(w0, v0.x, acc.x); acc.y = fmaf(w0, v0.y, acc.y);
        acc.z = fmaf(w0, v0.z, acc.z); acc.w = fmaf(w0, v0.w, acc.w);
        acc.x = fmaf(w1, v1.x, acc.x); acc.y = fmaf(w1, v1.y, acc.y);
        acc.z = fmaf(w1, v1.z, acc.z); acc.w = fmaf(w1, v1.w, acc.w);
        acc.x = fmaf(w2, v2.x, acc.x); acc.y = fmaf(w2, v2.y, acc.y);
        acc.z = fmaf(w2, v2.z, acc.z); acc.w = fmaf(w2, v2.w, acc.w);
        acc.x = fmaf(w3, v3.x, acc.x); acc.y = fmaf(w3, v3.y, acc.y);
        acc.z = fmaf(w3, v3.z, acc.z); acc.w = fmaf(w3, v3.w, acc.w);
    }
    for (; e < e1; e++) {
        uint2 m = g_edge[e];
        float w = __uint_as_float(m.y);
        float4 v = u2f4(in2[m.x * 32 + lane]);
        acc.x = fmaf(w, v.x, acc.x); acc.y = fmaf(w, v.y, acc.y);
        acc.z = fmaf(w, v.z, acc.z); acc.w = fmaf(w, v.w, acc.w);
    }

    float4 b = reinterpret_cast<const float4*>(bias)[lane];
    acc.x = fmaxf(acc.x + b.x, 0.f);
    acc.y = fmaxf(acc.y + b.y, 0.f);
    acc.z = fmaxf(acc.z + b.z, 0.f);
    acc.w = fmaxf(acc.w + b.w, 0.f);

    if (POOL) {
        int g = batch[node];
        float* p = &g_pool[g * D + lane * 4];
        atomicAdd(p + 0, acc.x);
        atomicAdd(p + 1, acc.y);
        atomicAdd(p + 2, acc.z);
        atomicAdd(p + 3, acc.w);
    } else {
        reinterpret_cast<float4*>(g_bufB)[node * 32 + lane] = acc;   // h1 fp32
    }
}

// -------- head: out[g] = (pool[g]/count) . Wh + bh --------
__global__ void final_kernel(const float* __restrict__ Wh,
                             const float* __restrict__ bh,
                             float* __restrict__ out) {
    __shared__ float red[128];
    const int g = blockIdx.x;
    const int t = threadIdx.x;
    float c = (float)g_gcnt[g];
    c = fmaxf(c, 1.0f);
    float v = (g_pool[g * D + t] / c) * Wh[t];
    red[t] = v;
    __syncthreads();
    for (int s = 64; s > 0; s >>= 1) {
        if (t < s) red[t] += red[t + s];
        __syncthreads();
    }
    if (t == 0) out[g] = red[0] + bh[0];
}

extern "C" void kernel_launch(void* const* d_in, const int* in_sizes, int n_in,
                              void* d_out, int out_size) {
    const float* x     = (const float*)d_in[0];
    const float* ew    = (const float*)d_in[1];
    const float* W1    = (const float*)d_in[2];
    const float* b1    = (const float*)d_in[3];
    const float* W2    = (const float*)d_in[4];
    const float* b2    = (const float*)d_in[5];
    const float* Wh    = (const float*)d_in[6];
    const float* bh    = (const float*)d_in[7];
    const int*   ei    = (const int*)d_in[8];
    const int*   batch = (const int*)d_in[9];
    float*       out   = (float*)d_out;

    const int NB_N = (N_NODES + 255) / 256;   // 196
    const int NB_E = (N_EDGES + 255) / 256;   // 3125
    const int NB_G = (N_NODES + BM - 1) / BM; // 782

    static bool attr_set = false;
    if (!attr_set) {
        cudaFuncSetAttribute(gemm_mma, cudaFuncAttributeMaxDynamicSharedMemorySize,
                             GEMM_SMEM_BYTES);
        attr_set = true;
    }

    init_kernel<<<NB_N, 256>>>(W1, W2);
    edge_deg_kernel<<<NB_E, 256>>>(ei, ew);
    dinv_kernel<<<NB_N, 256>>>(batch);
    gemm_mma<<<NB_G, 256, GEMM_SMEM_BYTES>>>(x, 0);        // layer-1 GEMM (profiled slot)
    scan1_kernel<<<NB_SCAN, 256>>>();
    scan2_kernel<<<1, 256>>>();
    scan3_kernel<<<NB_SCAN, 256>>>();
    fill_kernel<<<NB_E, 256>>>(ei, ew);

    agg_kernel<false><<<N_NODES / 8, 256>>>(b1, batch);
    gemm_mma<<<NB_G, 256, GEMM_SMEM_BYTES>>>(nullptr, 1);  // layer-2 GEMM
    agg_kernel<true><<<N_NODES / 8, 256>>>(b2, batch);

    final_kernel<<<N_GR, 128>>>(Wh, bh, out);
}